// round 4
// baseline (speedup 1.0000x reference)
#include <cuda_runtime.h>
#include <math_constants.h>

// Problem constants (pinned by the dataset)
#define BATCH   32
#define HEADS   32
#define HKV     8
#define GQA     4      // HEADS / HKV
#define DIM     128    // head dim, == Lv
#define S_MAX   8      // max kv splits
#define NWARP   4
#define NTHREAD 128

__global__ __launch_bounds__(NTHREAD, 8)
void decode_attn_stage1(const float* __restrict__ q,
                        const float* __restrict__ k_buf,
                        const float* __restrict__ v_buf,
                        const int*   __restrict__ kv_indptr,
                        const int*   __restrict__ kv_indices,
                        const int*   __restrict__ num_kv_splits,
                        float* __restrict__ att_out,   // [B, H, S, DIM]
                        float* __restrict__ att_lse)   // [B, H, S]
{
    const int bid  = blockIdx.x;
    const int s    = bid % S_MAX;
    const int hkv  = (bid / S_MAX) % HKV;
    const int b    = bid / (S_MAX * HKV);

    const int tid  = threadIdx.x;
    const int lane = tid & 31;
    const int w    = tid >> 5;

    const int p0      = kv_indptr[b];
    const int seq_len = kv_indptr[b + 1] - p0;
    const int nsp     = num_kv_splits[b];
    // kv_len_per_split = cdiv(cdiv(seq_len, nsp), 32) * 32
    const int klps = (((seq_len + nsp - 1) / nsp) + 31) / 32 * 32;
    const int t0 = s * klps;
    const int t1 = min(t0 + klps, seq_len);

    // Load q fragments (pre-scaled by sm_scale)
    const float sm_scale = 0.08838834764831845f;  // 1/sqrt(128)
    float4 q4[GQA];
#pragma unroll
    for (int g = 0; g < GQA; g++) {
        const float4* qp = reinterpret_cast<const float4*>(
            q + ((size_t)b * HEADS + hkv * GQA + g) * DIM);
        float4 t = qp[lane];
        q4[g] = make_float4(t.x * sm_scale, t.y * sm_scale,
                            t.z * sm_scale, t.w * sm_scale);
    }

    float  m[GQA], l[GQA];
    float4 acc[GQA];
#pragma unroll
    for (int g = 0; g < GQA; g++) {
        m[g] = -CUDART_INF_F;
        l[g] = 0.0f;
        acc[g] = make_float4(0.f, 0.f, 0.f, 0.f);
    }

    // Main loop: one warp per token, strided by NWARP
    for (int t = t0 + w; t < t1; t += NWARP) {
        const int loc = __ldg(kv_indices + p0 + t);
        const size_t row = ((size_t)loc * HKV + hkv) * DIM;
        const float4 k4 = reinterpret_cast<const float4*>(k_buf + row)[lane];
        const float4 v4 = reinterpret_cast<const float4*>(v_buf + row)[lane];

        float d[GQA];
#pragma unroll
        for (int g = 0; g < GQA; g++) {
            d[g] = q4[g].x * k4.x;
            d[g] = fmaf(q4[g].y, k4.y, d[g]);
            d[g] = fmaf(q4[g].z, k4.z, d[g]);
            d[g] = fmaf(q4[g].w, k4.w, d[g]);
        }
#pragma unroll
        for (int off = 16; off > 0; off >>= 1) {
#pragma unroll
            for (int g = 0; g < GQA; g++)
                d[g] += __shfl_xor_sync(0xFFFFFFFFu, d[g], off);
        }
#pragma unroll
        for (int g = 0; g < GQA; g++) {
            const float mn = fmaxf(m[g], d[g]);
            const float sc = __expf(m[g] - mn);   // exp(-inf)=0 on first token
            const float p  = __expf(d[g] - mn);
            l[g] = l[g] * sc + p;
            acc[g].x = fmaf(p, v4.x, acc[g].x * sc);
            acc[g].y = fmaf(p, v4.y, acc[g].y * sc);
            acc[g].z = fmaf(p, v4.z, acc[g].z * sc);
            acc[g].w = fmaf(p, v4.w, acc[g].w * sc);
            m[g] = mn;
        }
    }

    // Cross-warp combine via shared memory
    __shared__ float  sm_m[NWARP][GQA];
    __shared__ float  sm_l[NWARP][GQA];
    __shared__ float4 sm_acc[NWARP][GQA][32];

    if (lane == 0) {
#pragma unroll
        for (int g = 0; g < GQA; g++) {
            sm_m[w][g] = m[g];
            sm_l[w][g] = l[g];
        }
    }
#pragma unroll
    for (int g = 0; g < GQA; g++)
        sm_acc[w][g][lane] = acc[g];
    __syncthreads();

    // Warp g finalizes head g
    const int g = w;
    float mf = -CUDART_INF_F;
#pragma unroll
    for (int ww = 0; ww < NWARP; ww++)
        mf = fmaxf(mf, sm_m[ww][g]);

    float  lf = 0.0f;
    float4 af = make_float4(0.f, 0.f, 0.f, 0.f);
#pragma unroll
    for (int ww = 0; ww < NWARP; ww++) {
        const float mw = sm_m[ww][g];
        const float sc = (mw == -CUDART_INF_F) ? 0.0f : __expf(mw - mf);
        lf += sm_l[ww][g] * sc;
        const float4 a = sm_acc[ww][g][lane];
        af.x = fmaf(a.x, sc, af.x);
        af.y = fmaf(a.y, sc, af.y);
        af.z = fmaf(a.z, sc, af.z);
        af.w = fmaf(a.w, sc, af.w);
    }

    const float inv = (lf > 0.0f) ? (1.0f / lf) : 0.0f;
    const int   h   = hkv * GQA + g;
    const size_t ob = (((size_t)b * HEADS + h) * S_MAX + s) * DIM;
    float4 o = make_float4(af.x * inv, af.y * inv, af.z * inv, af.w * inv);
    reinterpret_cast<float4*>(att_out + ob)[lane] = o;
    if (lane == 0)
        att_lse[((size_t)b * HEADS + h) * S_MAX + s] = mf + logf(lf);
}

extern "C" void kernel_launch(void* const* d_in, const int* in_sizes, int n_in,
                              void* d_out, int out_size) {
    const float* q          = (const float*)d_in[0];
    const float* k_buffer   = (const float*)d_in[1];
    const float* v_buffer   = (const float*)d_in[2];
    const int*   kv_indptr  = (const int*)d_in[3];
    const int*   kv_indices = (const int*)d_in[4];
    const int*   nks        = (const int*)d_in[5];

    float* att_out = (float*)d_out;                                  // B*H*S*DIM
    float* att_lse = att_out + (size_t)BATCH * HEADS * S_MAX * DIM;  // B*H*S

    dim3 grid(BATCH * HKV * S_MAX);
    dim3 block(NTHREAD);
    decode_attn_stage1<<<grid, block>>>(q, k_buffer, v_buffer,
                                        kv_indptr, kv_indices, nks,
                                        att_out, att_lse);
}

// round 5
// speedup vs baseline: 1.2732x; 1.2732x over previous
#include <cuda_runtime.h>
#include <math_constants.h>

// Problem constants (pinned by the dataset)
#define BATCH   32
#define HEADS   32
#define HKV     8
#define GQA     4      // HEADS / HKV
#define DIM     128    // head dim, == Lv
#define S_MAX   8      // max kv splits
#define NWARP   4
#define NTHREAD 128

__global__ __launch_bounds__(NTHREAD, 6)
void decode_attn_stage1(const float* __restrict__ q,
                        const float* __restrict__ k_buf,
                        const float* __restrict__ v_buf,
                        const int*   __restrict__ kv_indptr,
                        const int*   __restrict__ kv_indices,
                        const int*   __restrict__ num_kv_splits,
                        float* __restrict__ att_out,   // [B, H, S, DIM]
                        float* __restrict__ att_lse)   // [B, H, S]
{
    const int bid  = blockIdx.x;
    const int s    = bid % S_MAX;
    const int hkv  = (bid / S_MAX) % HKV;
    const int b    = bid / (S_MAX * HKV);

    const int tid  = threadIdx.x;
    const int lane = tid & 31;
    const int w    = tid >> 5;

    const int p0      = kv_indptr[b];
    const int seq_len = kv_indptr[b + 1] - p0;
    const int nsp     = num_kv_splits[b];
    // kv_len_per_split = cdiv(cdiv(seq_len, nsp), 32) * 32
    const int klps = (((seq_len + nsp - 1) / nsp) + 31) / 32 * 32;
    const int t0 = s * klps;
    const int t1 = min(t0 + klps, seq_len);

    // Load q fragments (pre-scaled by sm_scale)
    const float sm_scale = 0.08838834764831845f;  // 1/sqrt(128)
    float4 q4[GQA];
#pragma unroll
    for (int g = 0; g < GQA; g++) {
        const float4* qp = reinterpret_cast<const float4*>(
            q + ((size_t)b * HEADS + hkv * GQA + g) * DIM);
        float4 t = qp[lane];
        q4[g] = make_float4(t.x * sm_scale, t.y * sm_scale,
                            t.z * sm_scale, t.w * sm_scale);
    }

    float  m[GQA], l[GQA];
    float4 acc[GQA];
#pragma unroll
    for (int g = 0; g < GQA; g++) {
        m[g] = -CUDART_INF_F;
        l[g] = 0.0f;
        acc[g] = make_float4(0.f, 0.f, 0.f, 0.f);
    }

    const int* idx = kv_indices + p0;

    // Main loop: each warp consumes TWO tokens per iteration (t and t+NWARP).
    // 4x16B loads in flight per warp; shuffle reduction runs 8 independent
    // chains per round; softmax update fused across the token pair.
    for (int t = t0 + w; t < t1; t += 2 * NWARP) {
        const int  tb   = t + NWARP;
        const bool hasB = (tb < t1);

        const int locA = __ldg(idx + t);
        const int locB = hasB ? __ldg(idx + tb) : locA;

        const size_t rowA = ((size_t)locA * HKV + hkv) * DIM;
        const size_t rowB = ((size_t)locB * HKV + hkv) * DIM;

        // Issue all four row loads before any compute.
        const float4 kA = reinterpret_cast<const float4*>(k_buf + rowA)[lane];
        const float4 kB = reinterpret_cast<const float4*>(k_buf + rowB)[lane];
        const float4 vA = reinterpret_cast<const float4*>(v_buf + rowA)[lane];
        const float4 vB = reinterpret_cast<const float4*>(v_buf + rowB)[lane];

        float dA[GQA], dB[GQA];
#pragma unroll
        for (int g = 0; g < GQA; g++) {
            float a = q4[g].x * kA.x;
            a = fmaf(q4[g].y, kA.y, a);
            a = fmaf(q4[g].z, kA.z, a);
            a = fmaf(q4[g].w, kA.w, a);
            dA[g] = a;
            float c = q4[g].x * kB.x;
            c = fmaf(q4[g].y, kB.y, c);
            c = fmaf(q4[g].z, kB.z, c);
            c = fmaf(q4[g].w, kB.w, c);
            dB[g] = c;
        }
#pragma unroll
        for (int off = 16; off > 0; off >>= 1) {
#pragma unroll
            for (int g = 0; g < GQA; g++) {
                dA[g] += __shfl_xor_sync(0xFFFFFFFFu, dA[g], off);
                dB[g] += __shfl_xor_sync(0xFFFFFFFFu, dB[g], off);
            }
        }

#pragma unroll
        for (int g = 0; g < GQA; g++) {
            const float db = hasB ? dB[g] : -CUDART_INF_F;
            const float mn = fmaxf(m[g], fmaxf(dA[g], db));
            const float sc = __expf(m[g] - mn);   // exp(-inf)=0 on first pair
            const float pA = __expf(dA[g] - mn);
            const float pB = __expf(db    - mn);  // 0 when !hasB
            l[g] = fmaf(l[g], sc, pA + pB);
            acc[g].x = fmaf(pB, vB.x, fmaf(pA, vA.x, acc[g].x * sc));
            acc[g].y = fmaf(pB, vB.y, fmaf(pA, vA.y, acc[g].y * sc));
            acc[g].z = fmaf(pB, vB.z, fmaf(pA, vA.z, acc[g].z * sc));
            acc[g].w = fmaf(pB, vB.w, fmaf(pA, vA.w, acc[g].w * sc));
            m[g] = mn;
        }
    }

    // Cross-warp combine via shared memory
    __shared__ float  sm_m[NWARP][GQA];
    __shared__ float  sm_l[NWARP][GQA];
    __shared__ float4 sm_acc[NWARP][GQA][32];

    if (lane == 0) {
#pragma unroll
        for (int g = 0; g < GQA; g++) {
            sm_m[w][g] = m[g];
            sm_l[w][g] = l[g];
        }
    }
#pragma unroll
    for (int g = 0; g < GQA; g++)
        sm_acc[w][g][lane] = acc[g];
    __syncthreads();

    // Warp g finalizes head g
    const int g = w;
    float mf = -CUDART_INF_F;
#pragma unroll
    for (int ww = 0; ww < NWARP; ww++)
        mf = fmaxf(mf, sm_m[ww][g]);

    float  lf = 0.0f;
    float4 af = make_float4(0.f, 0.f, 0.f, 0.f);
#pragma unroll
    for (int ww = 0; ww < NWARP; ww++) {
        const float mw = sm_m[ww][g];
        const float sc = (mw == -CUDART_INF_F) ? 0.0f : __expf(mw - mf);
        lf += sm_l[ww][g] * sc;
        const float4 a = sm_acc[ww][g][lane];
        af.x = fmaf(a.x, sc, af.x);
        af.y = fmaf(a.y, sc, af.y);
        af.z = fmaf(a.z, sc, af.z);
        af.w = fmaf(a.w, sc, af.w);
    }

    const float inv = (lf > 0.0f) ? (1.0f / lf) : 0.0f;
    const int   h   = hkv * GQA + g;
    const size_t ob = (((size_t)b * HEADS + h) * S_MAX + s) * DIM;
    float4 o = make_float4(af.x * inv, af.y * inv, af.z * inv, af.w * inv);
    reinterpret_cast<float4*>(att_out + ob)[lane] = o;
    if (lane == 0)
        att_lse[((size_t)b * HEADS + h) * S_MAX + s] = mf + logf(lf);
}

extern "C" void kernel_launch(void* const* d_in, const int* in_sizes, int n_in,
                              void* d_out, int out_size) {
    const float* q          = (const float*)d_in[0];
    const float* k_buffer   = (const float*)d_in[1];
    const float* v_buffer   = (const float*)d_in[2];
    const int*   kv_indptr  = (const int*)d_in[3];
    const int*   kv_indices = (const int*)d_in[4];
    const int*   nks        = (const int*)d_in[5];

    float* att_out = (float*)d_out;                                  // B*H*S*DIM
    float* att_lse = att_out + (size_t)BATCH * HEADS * S_MAX * DIM;  // B*H*S

    dim3 grid(BATCH * HKV * S_MAX);
    dim3 block(NTHREAD);
    decode_attn_stage1<<<grid, block>>>(q, k_buffer, v_buffer,
                                        kv_indptr, kv_indices, nks,
                                        att_out, att_lse);
}

// round 6
// speedup vs baseline: 1.5258x; 1.1984x over previous
#include <cuda_runtime.h>
#include <math_constants.h>

// Problem constants (pinned by the dataset)
#define BATCH   32
#define HEADS   32
#define HKV     8
#define GQA     4      // HEADS / HKV
#define DIM     128    // head dim, == Lv
#define S_MAX   8      // max kv splits
#define NWARP   4
#define NTHREAD 128

__global__ __launch_bounds__(NTHREAD, 5)
void decode_attn_stage1(const float* __restrict__ q,
                        const float* __restrict__ k_buf,
                        const float* __restrict__ v_buf,
                        const int*   __restrict__ kv_indptr,
                        const int*   __restrict__ kv_indices,
                        const int*   __restrict__ num_kv_splits,
                        float* __restrict__ att_out,   // [B, H, S, DIM]
                        float* __restrict__ att_lse)   // [B, H, S]
{
    const int bid  = blockIdx.x;
    const int s    = bid % S_MAX;
    const int hkv  = (bid / S_MAX) % HKV;
    const int b    = bid / (S_MAX * HKV);

    const int tid  = threadIdx.x;
    const int lane = tid & 31;
    const int w    = tid >> 5;

    const int p0      = kv_indptr[b];
    const int seq_len = kv_indptr[b + 1] - p0;
    const int nsp     = num_kv_splits[b];
    // kv_len_per_split = cdiv(cdiv(seq_len, nsp), 32) * 32
    const int klps = (((seq_len + nsp - 1) / nsp) + 31) / 32 * 32;
    const int t0 = s * klps;
    const int t1 = min(t0 + klps, seq_len);

    // q pre-scaled by sm_scale * log2(e): logits produced directly in log2
    // domain so the online softmax uses exp2f (pure MUFU, no extra FMUL).
    const float qscale = 0.08838834764831845f * 1.4426950408889634f;
    float4 q4[GQA];
#pragma unroll
    for (int g = 0; g < GQA; g++) {
        const float4* qp = reinterpret_cast<const float4*>(
            q + ((size_t)b * HEADS + hkv * GQA + g) * DIM);
        float4 t = qp[lane];
        q4[g] = make_float4(t.x * qscale, t.y * qscale,
                            t.z * qscale, t.w * qscale);
    }

    float  m[GQA], l[GQA];          // m in log2 units
    float4 acc[GQA];
#pragma unroll
    for (int g = 0; g < GQA; g++) {
        m[g] = -CUDART_INF_F;
        l[g] = 0.0f;
        acc[g] = make_float4(0.f, 0.f, 0.f, 0.f);
    }

    const int* idx = kv_indices + p0;

    // Main loop: each warp consumes FOUR tokens per iteration.
    // 8 x 16B loads issued back-to-back; shuffle reduction runs 16
    // independent chains per round; softmax update fused across 4 tokens.
    for (int t = t0 + w; t < t1; t += 4 * NWARP) {
        const int tA = t;
        const int tB = t + 1 * NWARP;
        const int tC = t + 2 * NWARP;
        const int tD = t + 3 * NWARP;
        const bool hB = (tB < t1), hC = (tC < t1), hD = (tD < t1);

        const int locA = __ldg(idx + tA);
        const int locB = hB ? __ldg(idx + tB) : locA;
        const int locC = hC ? __ldg(idx + tC) : locA;
        const int locD = hD ? __ldg(idx + tD) : locA;

        // 32-bit element offsets: pool rows * HKV * DIM <= 2^26, fits int.
        const int rowA = (locA * HKV + hkv) * DIM;
        const int rowB = (locB * HKV + hkv) * DIM;
        const int rowC = (locC * HKV + hkv) * DIM;
        const int rowD = (locD * HKV + hkv) * DIM;

        const float4 kA = reinterpret_cast<const float4*>(k_buf + rowA)[lane];
        const float4 kB = reinterpret_cast<const float4*>(k_buf + rowB)[lane];
        const float4 kC = reinterpret_cast<const float4*>(k_buf + rowC)[lane];
        const float4 kD = reinterpret_cast<const float4*>(k_buf + rowD)[lane];
        const float4 vA = reinterpret_cast<const float4*>(v_buf + rowA)[lane];
        const float4 vB = reinterpret_cast<const float4*>(v_buf + rowB)[lane];
        const float4 vC = reinterpret_cast<const float4*>(v_buf + rowC)[lane];
        const float4 vD = reinterpret_cast<const float4*>(v_buf + rowD)[lane];

        float dA[GQA], dB[GQA], dC[GQA], dD[GQA];
#pragma unroll
        for (int g = 0; g < GQA; g++) {
            float a = q4[g].x * kA.x;
            a = fmaf(q4[g].y, kA.y, a); a = fmaf(q4[g].z, kA.z, a);
            a = fmaf(q4[g].w, kA.w, a); dA[g] = a;
            float c = q4[g].x * kB.x;
            c = fmaf(q4[g].y, kB.y, c); c = fmaf(q4[g].z, kB.z, c);
            c = fmaf(q4[g].w, kB.w, c); dB[g] = c;
            float e = q4[g].x * kC.x;
            e = fmaf(q4[g].y, kC.y, e); e = fmaf(q4[g].z, kC.z, e);
            e = fmaf(q4[g].w, kC.w, e); dC[g] = e;
            float f = q4[g].x * kD.x;
            f = fmaf(q4[g].y, kD.y, f); f = fmaf(q4[g].z, kD.z, f);
            f = fmaf(q4[g].w, kD.w, f); dD[g] = f;
        }
#pragma unroll
        for (int off = 16; off > 0; off >>= 1) {
#pragma unroll
            for (int g = 0; g < GQA; g++) {
                dA[g] += __shfl_xor_sync(0xFFFFFFFFu, dA[g], off);
                dB[g] += __shfl_xor_sync(0xFFFFFFFFu, dB[g], off);
                dC[g] += __shfl_xor_sync(0xFFFFFFFFu, dC[g], off);
                dD[g] += __shfl_xor_sync(0xFFFFFFFFu, dD[g], off);
            }
        }

#pragma unroll
        for (int g = 0; g < GQA; g++) {
            const float db = hB ? dB[g] : -CUDART_INF_F;
            const float dc = hC ? dC[g] : -CUDART_INF_F;
            const float dd = hD ? dD[g] : -CUDART_INF_F;
            const float mn = fmaxf(fmaxf(m[g], dA[g]),
                                   fmaxf(fmaxf(db, dc), dd));
            const float sc = exp2f(m[g] - mn);   // exp2(-inf)=0 on first iter
            const float pA = exp2f(dA[g] - mn);
            const float pB = exp2f(db    - mn);
            const float pC = exp2f(dc    - mn);
            const float pD = exp2f(dd    - mn);
            l[g] = fmaf(l[g], sc, (pA + pB) + (pC + pD));
            acc[g].x = fmaf(pD, vD.x, fmaf(pC, vC.x,
                       fmaf(pB, vB.x, fmaf(pA, vA.x, acc[g].x * sc))));
            acc[g].y = fmaf(pD, vD.y, fmaf(pC, vC.y,
                       fmaf(pB, vB.y, fmaf(pA, vA.y, acc[g].y * sc))));
            acc[g].z = fmaf(pD, vD.z, fmaf(pC, vC.z,
                       fmaf(pB, vB.z, fmaf(pA, vA.z, acc[g].z * sc))));
            acc[g].w = fmaf(pD, vD.w, fmaf(pC, vC.w,
                       fmaf(pB, vB.w, fmaf(pA, vA.w, acc[g].w * sc))));
            m[g] = mn;
        }
    }

    // Cross-warp combine via shared memory
    __shared__ float  sm_m[NWARP][GQA];
    __shared__ float  sm_l[NWARP][GQA];
    __shared__ float4 sm_acc[NWARP][GQA][32];

    if (lane == 0) {
#pragma unroll
        for (int g = 0; g < GQA; g++) {
            sm_m[w][g] = m[g];
            sm_l[w][g] = l[g];
        }
    }
#pragma unroll
    for (int g = 0; g < GQA; g++)
        sm_acc[w][g][lane] = acc[g];
    __syncthreads();

    // Warp g finalizes head g
    const int g = w;
    float mf = -CUDART_INF_F;
#pragma unroll
    for (int ww = 0; ww < NWARP; ww++)
        mf = fmaxf(mf, sm_m[ww][g]);

    float  lf = 0.0f;
    float4 af = make_float4(0.f, 0.f, 0.f, 0.f);
#pragma unroll
    for (int ww = 0; ww < NWARP; ww++) {
        const float mw = sm_m[ww][g];
        const float sc = (mw == -CUDART_INF_F) ? 0.0f : exp2f(mw - mf);
        lf += sm_l[ww][g] * sc;
        const float4 a = sm_acc[ww][g][lane];
        af.x = fmaf(a.x, sc, af.x);
        af.y = fmaf(a.y, sc, af.y);
        af.z = fmaf(a.z, sc, af.z);
        af.w = fmaf(a.w, sc, af.w);
    }

    const float inv = (lf > 0.0f) ? (1.0f / lf) : 0.0f;
    const int   h   = hkv * GQA + g;
    const size_t ob = (((size_t)b * HEADS + h) * S_MAX + s) * DIM;
    float4 o = make_float4(af.x * inv, af.y * inv, af.z * inv, af.w * inv);
    reinterpret_cast<float4*>(att_out + ob)[lane] = o;
    if (lane == 0) {
        // m is in log2 units: lse = m*ln2 + ln(lf)
        att_lse[((size_t)b * HEADS + h) * S_MAX + s] =
            mf * 0.6931471805599453f + logf(lf);
    }
}

extern "C" void kernel_launch(void* const* d_in, const int* in_sizes, int n_in,
                              void* d_out, int out_size) {
    const float* q          = (const float*)d_in[0];
    const float* k_buffer   = (const float*)d_in[1];
    const float* v_buffer   = (const float*)d_in[2];
    const int*   kv_indptr  = (const int*)d_in[3];
    const int*   kv_indices = (const int*)d_in[4];
    const int*   nks        = (const int*)d_in[5];

    float* att_out = (float*)d_out;                                  // B*H*S*DIM
    float* att_lse = att_out + (size_t)BATCH * HEADS * S_MAX * DIM;  // B*H*S

    dim3 grid(BATCH * HKV * S_MAX);
    dim3 block(NTHREAD);
    decode_attn_stage1<<<grid, block>>>(q, k_buffer, v_buffer,
                                        kv_indptr, kv_indices, nks,
                                        att_out, att_lse);
}

// round 8
// speedup vs baseline: 1.5741x; 1.0317x over previous
#include <cuda_runtime.h>
#include <math_constants.h>
#include <cstdint>

// Problem constants (pinned by the dataset)
#define BATCH   32
#define HEADS   32
#define HKV     8
#define GQA     4      // HEADS / HKV
#define DIM     128    // head dim, == Lv
#define S_MAX   8      // max kv splits
#define NWARP   4
#define NTHREAD 128
#define STAGES  3      // cp.async pipeline depth
#define TPI     4      // tokens per stage per warp
#define CHUNK   (NWARP * TPI)   // 16 tokens per block iteration

// smem staging: [NWARP][STAGES][TPI][64] float4  (64 = 32 K + 32 V)
// = 4*3*4*64*16 B = 49152 B (exactly the 48KB dynamic default)
#define STAGE_F4 (TPI * 64)

__global__ __launch_bounds__(NTHREAD, 4)
void decode_attn_stage1(const float* __restrict__ q,
                        const float* __restrict__ k_buf,
                        const float* __restrict__ v_buf,
                        const int*   __restrict__ kv_indptr,
                        const int*   __restrict__ kv_indices,
                        const int*   __restrict__ num_kv_splits,
                        float* __restrict__ att_out,   // [B, H, S, DIM]
                        float* __restrict__ att_lse)   // [B, H, S]
{
    extern __shared__ float4 sbuf[];

    const int bid  = blockIdx.x;
    const int s    = bid % S_MAX;
    const int hkv  = (bid / S_MAX) % HKV;
    const int b    = bid / (S_MAX * HKV);

    const int tid  = threadIdx.x;
    const int lane = tid & 31;
    const int w    = tid >> 5;

    const int p0      = kv_indptr[b];
    const int seq_len = kv_indptr[b + 1] - p0;
    const int nsp     = num_kv_splits[b];
    const int klps = (((seq_len + nsp - 1) / nsp) + 31) / 32 * 32;
    const int t0 = s * klps;
    const int t1 = min(t0 + klps, seq_len);
    const int ntok = t1 - t0;
    const int n_iters = (ntok + CHUNK - 1) / CHUNK;

    // q pre-scaled by sm_scale * log2(e): softmax in log2 domain (exp2f).
    const float qscale = 0.08838834764831845f * 1.4426950408889634f;
    float4 q4[GQA];
#pragma unroll
    for (int g = 0; g < GQA; g++) {
        const float4* qp = reinterpret_cast<const float4*>(
            q + ((size_t)b * HEADS + hkv * GQA + g) * DIM);
        float4 t = qp[lane];
        q4[g] = make_float4(t.x * qscale, t.y * qscale,
                            t.z * qscale, t.w * qscale);
    }

    float  m[GQA], l[GQA];          // m in log2 units
    float4 acc[GQA];
#pragma unroll
    for (int g = 0; g < GQA; g++) {
        m[g] = -CUDART_INF_F;
        l[g] = 0.0f;
        acc[g] = make_float4(0.f, 0.f, 0.f, 0.f);
    }

    const int* idx = kv_indices + p0;
    const uint32_t sbase =
        (uint32_t)__cvta_generic_to_shared(sbuf) +
        (uint32_t)(w * STAGES) * STAGE_F4 * 16;

    // Issue one stage's copies (K row + V row per token) and commit a group.
    auto issue_stage = [&](int st) {
        const uint32_t so = sbase + (uint32_t)(st % STAGES) * (STAGE_F4 * 16);
#pragma unroll
        for (int j = 0; j < TPI; j++) {
            const int tt = t0 + st * CHUNK + w * TPI + j;
            if (tt < t1) {
                const int loc = __ldg(idx + tt);
                // 32-bit element offset: pool*HKV*DIM fits in int
                const int row = (loc * HKV + hkv) * DIM + lane * 4;
                const uint32_t d = so + (uint32_t)(j * 64 + lane) * 16;
                asm volatile("cp.async.cg.shared.global [%0], [%1], 16;"
                             :: "r"(d), "l"(k_buf + row));
                asm volatile("cp.async.cg.shared.global [%0], [%1], 16;"
                             :: "r"(d + 512), "l"(v_buf + row));
            }
        }
        asm volatile("cp.async.commit_group;");
    };

    // Prologue: fill STAGES-1 stages.
#pragma unroll
    for (int st = 0; st < STAGES - 1; st++)
        issue_stage(st);

    for (int i = 0; i < n_iters; i++) {
        issue_stage(i + STAGES - 1);                 // prefetch (guarded inside)
        asm volatile("cp.async.wait_group %0;" :: "n"(STAGES - 1));

        const float4* kv = sbuf + (w * STAGES + (i % STAGES)) * STAGE_F4;
        const int tb = t0 + i * CHUNK + w * TPI;
        const bool hA = (tb + 0) < t1;
        const bool hB = (tb + 1) < t1;
        const bool hC = (tb + 2) < t1;
        const bool hD = (tb + 3) < t1;

        const float4 kA = kv[0 * 64 + lane];
        const float4 kB = kv[1 * 64 + lane];
        const float4 kC = kv[2 * 64 + lane];
        const float4 kD = kv[3 * 64 + lane];

        float dA[GQA], dB[GQA], dC[GQA], dD[GQA];
#pragma unroll
        for (int g = 0; g < GQA; g++) {
            float a = q4[g].x * kA.x;
            a = fmaf(q4[g].y, kA.y, a); a = fmaf(q4[g].z, kA.z, a);
            a = fmaf(q4[g].w, kA.w, a); dA[g] = a;
            float c = q4[g].x * kB.x;
            c = fmaf(q4[g].y, kB.y, c); c = fmaf(q4[g].z, kB.z, c);
            c = fmaf(q4[g].w, kB.w, c); dB[g] = c;
            float e = q4[g].x * kC.x;
            e = fmaf(q4[g].y, kC.y, e); e = fmaf(q4[g].z, kC.z, e);
            e = fmaf(q4[g].w, kC.w, e); dC[g] = e;
            float f = q4[g].x * kD.x;
            f = fmaf(q4[g].y, kD.y, f); f = fmaf(q4[g].z, kD.z, f);
            f = fmaf(q4[g].w, kD.w, f); dD[g] = f;
        }
#pragma unroll
        for (int off = 16; off > 0; off >>= 1) {
#pragma unroll
            for (int g = 0; g < GQA; g++) {
                dA[g] += __shfl_xor_sync(0xFFFFFFFFu, dA[g], off);
                dB[g] += __shfl_xor_sync(0xFFFFFFFFu, dB[g], off);
                dC[g] += __shfl_xor_sync(0xFFFFFFFFu, dC[g], off);
                dD[g] += __shfl_xor_sync(0xFFFFFFFFu, dD[g], off);
            }
        }

        const float4 vA = kv[0 * 64 + 32 + lane];
        const float4 vB = kv[1 * 64 + 32 + lane];
        const float4 vC = kv[2 * 64 + 32 + lane];
        const float4 vD = kv[3 * 64 + 32 + lane];

#pragma unroll
        for (int g = 0; g < GQA; g++) {
            const float da = hA ? dA[g] : -CUDART_INF_F;
            const float db = hB ? dB[g] : -CUDART_INF_F;
            const float dc = hC ? dC[g] : -CUDART_INF_F;
            const float dd = hD ? dD[g] : -CUDART_INF_F;
            const float mn = fmaxf(fmaxf(m[g], da), fmaxf(fmaxf(db, dc), dd));
            // mnn guards the all-invalid case (mn = -inf): everything -> 0.
            const float mnn = (mn == -CUDART_INF_F) ? 0.0f : mn;
            const float sc = exp2f(m[g] - mnn);
            const float pA = exp2f(da - mnn);
            const float pB = exp2f(db - mnn);
            const float pC = exp2f(dc - mnn);
            const float pD = exp2f(dd - mnn);
            l[g] = fmaf(l[g], sc, (pA + pB) + (pC + pD));
            acc[g].x = fmaf(pD, vD.x, fmaf(pC, vC.x,
                       fmaf(pB, vB.x, fmaf(pA, vA.x, acc[g].x * sc))));
            acc[g].y = fmaf(pD, vD.y, fmaf(pC, vC.y,
                       fmaf(pB, vB.y, fmaf(pA, vA.y, acc[g].y * sc))));
            acc[g].z = fmaf(pD, vD.z, fmaf(pC, vC.z,
                       fmaf(pB, vB.z, fmaf(pA, vA.z, acc[g].z * sc))));
            acc[g].w = fmaf(pD, vD.w, fmaf(pC, vC.w,
                       fmaf(pB, vB.w, fmaf(pA, vA.w, acc[g].w * sc))));
            m[g] = mn;
        }
    }

    // Cross-warp combine, aliased into the staging buffer.
    __syncthreads();
    float*  sm_m   = (float*)sbuf;                       // [NWARP][GQA]
    float*  sm_l   = sm_m + NWARP * GQA;                 // [NWARP][GQA]
    float4* sm_acc = (float4*)(sm_l + NWARP * GQA);      // [NWARP][GQA][32]

    if (lane == 0) {
#pragma unroll
        for (int g = 0; g < GQA; g++) {
            sm_m[w * GQA + g] = m[g];
            sm_l[w * GQA + g] = l[g];
        }
    }
#pragma unroll
    for (int g = 0; g < GQA; g++)
        sm_acc[(w * GQA + g) * 32 + lane] = acc[g];
    __syncthreads();

    // Warp g finalizes head g
    const int g = w;
    float mf = -CUDART_INF_F;
#pragma unroll
    for (int ww = 0; ww < NWARP; ww++)
        mf = fmaxf(mf, sm_m[ww * GQA + g]);

    float  lf = 0.0f;
    float4 af = make_float4(0.f, 0.f, 0.f, 0.f);
#pragma unroll
    for (int ww = 0; ww < NWARP; ww++) {
        const float mw = sm_m[ww * GQA + g];
        const float sc = (mw == -CUDART_INF_F) ? 0.0f : exp2f(mw - mf);
        lf += sm_l[ww * GQA + g] * sc;
        const float4 a = sm_acc[(ww * GQA + g) * 32 + lane];
        af.x = fmaf(a.x, sc, af.x);
        af.y = fmaf(a.y, sc, af.y);
        af.z = fmaf(a.z, sc, af.z);
        af.w = fmaf(a.w, sc, af.w);
    }

    const float inv = (lf > 0.0f) ? (1.0f / lf) : 0.0f;
    const int   h   = hkv * GQA + g;
    const size_t ob = (((size_t)b * HEADS + h) * S_MAX + s) * DIM;
    float4 o = make_float4(af.x * inv, af.y * inv, af.z * inv, af.w * inv);
    reinterpret_cast<float4*>(att_out + ob)[lane] = o;
    if (lane == 0) {
        // m is in log2 units: lse = m*ln2 + ln(lf)
        att_lse[((size_t)b * HEADS + h) * S_MAX + s] =
            mf * 0.6931471805599453f + logf(lf);
    }
}

extern "C" void kernel_launch(void* const* d_in, const int* in_sizes, int n_in,
                              void* d_out, int out_size) {
    const float* q          = (const float*)d_in[0];
    const float* k_buffer   = (const float*)d_in[1];
    const float* v_buffer   = (const float*)d_in[2];
    const int*   kv_indptr  = (const int*)d_in[3];
    const int*   kv_indices = (const int*)d_in[4];
    const int*   nks        = (const int*)d_in[5];

    float* att_out = (float*)d_out;                                  // B*H*S*DIM
    float* att_lse = att_out + (size_t)BATCH * HEADS * S_MAX * DIM;  // B*H*S

    const int smem = NWARP * STAGES * STAGE_F4 * sizeof(float4);     // 49152
    dim3 grid(BATCH * HKV * S_MAX);
    dim3 block(NTHREAD);
    decode_attn_stage1<<<grid, block, smem>>>(q, k_buffer, v_buffer,
                                              kv_indptr, kv_indices, nks,
                                              att_out, att_lse);
}

// round 9
// speedup vs baseline: 1.6338x; 1.0379x over previous
#include <cuda_runtime.h>
#include <math_constants.h>
#include <cstdint>

// Problem constants (pinned by the dataset)
#define BATCH   32
#define HEADS   32
#define HKV     8
#define GQA     4      // HEADS / HKV
#define DIM     128    // head dim, == Lv
#define S_MAX   8      // max kv splits
#define NWARP   4
#define NTHREAD 128
#define STAGES  2      // cp.async pipeline depth
#define TPI     4      // tokens per stage per warp
#define CHUNK   (NWARP * TPI)   // 16 tokens per block iteration

// smem staging: [NWARP][STAGES][TPI][64] float4  (64 = 32 K + 32 V)
// = 4*2*4*64*16 B = 32768 B  -> 5 CTAs/SM (reg-bound), ~31% occ
#define STAGE_F4 (TPI * 64)

__global__ __launch_bounds__(NTHREAD, 5)
void decode_attn_stage1(const float* __restrict__ q,
                        const float* __restrict__ k_buf,
                        const float* __restrict__ v_buf,
                        const int*   __restrict__ kv_indptr,
                        const int*   __restrict__ kv_indices,
                        const int*   __restrict__ num_kv_splits,
                        float* __restrict__ att_out,   // [B, H, S, DIM]
                        float* __restrict__ att_lse)   // [B, H, S]
{
    extern __shared__ float4 sbuf[];

    const int bid  = blockIdx.x;
    const int s    = bid % S_MAX;
    const int hkv  = (bid / S_MAX) % HKV;
    const int b    = bid / (S_MAX * HKV);

    const int tid  = threadIdx.x;
    const int lane = tid & 31;
    const int w    = tid >> 5;

    const int p0      = kv_indptr[b];
    const int seq_len = kv_indptr[b + 1] - p0;
    const int nsp     = num_kv_splits[b];
    const int klps = (((seq_len + nsp - 1) / nsp) + 31) / 32 * 32;
    const int t0 = s * klps;
    const int t1 = min(t0 + klps, seq_len);
    const int ntok = t1 - t0;
    const int nfull   = (ntok > 0) ? (ntok / CHUNK) : 0;       // unguarded iters
    const int n_iters = (ntok + CHUNK - 1) / CHUNK;            // total iters

    // q pre-scaled by sm_scale * log2(e): softmax in log2 domain (exp2f).
    const float qscale = 0.08838834764831845f * 1.4426950408889634f;
    float4 q4[GQA];
#pragma unroll
    for (int g = 0; g < GQA; g++) {
        const float4* qp = reinterpret_cast<const float4*>(
            q + ((size_t)b * HEADS + hkv * GQA + g) * DIM);
        float4 t = qp[lane];
        q4[g] = make_float4(t.x * qscale, t.y * qscale,
                            t.z * qscale, t.w * qscale);
    }

    float  m[GQA], l[GQA];          // m in log2 units
    float4 acc[GQA];
#pragma unroll
    for (int g = 0; g < GQA; g++) {
        m[g] = -CUDART_INF_F;
        l[g] = 0.0f;
        acc[g] = make_float4(0.f, 0.f, 0.f, 0.f);
    }

    const int* idx = kv_indices + p0;
    const uint32_t sbase =
        (uint32_t)__cvta_generic_to_shared(sbuf) +
        (uint32_t)(w * STAGES) * STAGE_F4 * 16;

    // Issue one stage's copies (K row + V row per token) and commit a group.
    // Full stages take the unguarded path: one int4 index load, no bounds checks.
    auto issue_stage = [&](int st) {
        const uint32_t so = sbase + (uint32_t)(st % STAGES) * (STAGE_F4 * 16);
        const int base = t0 + st * CHUNK + w * TPI;
        if (st < nfull) {
            // aligned: t0,CHUNK,TPI all multiples of 4
            const int4 loc4 = *reinterpret_cast<const int4*>(idx + base);
            const int rows[TPI] = {
                (loc4.x * HKV + hkv) * DIM + lane * 4,
                (loc4.y * HKV + hkv) * DIM + lane * 4,
                (loc4.z * HKV + hkv) * DIM + lane * 4,
                (loc4.w * HKV + hkv) * DIM + lane * 4 };
#pragma unroll
            for (int j = 0; j < TPI; j++) {
                const uint32_t d = so + (uint32_t)(j * 64 + lane) * 16;
                asm volatile("cp.async.cg.shared.global [%0], [%1], 16;"
                             :: "r"(d), "l"(k_buf + rows[j]));
                asm volatile("cp.async.cg.shared.global [%0], [%1], 16;"
                             :: "r"(d + 512), "l"(v_buf + rows[j]));
            }
        } else {
#pragma unroll
            for (int j = 0; j < TPI; j++) {
                const int tt = base + j;
                if (tt < t1) {
                    const int loc = __ldg(idx + tt);
                    const int row = (loc * HKV + hkv) * DIM + lane * 4;
                    const uint32_t d = so + (uint32_t)(j * 64 + lane) * 16;
                    asm volatile("cp.async.cg.shared.global [%0], [%1], 16;"
                                 :: "r"(d), "l"(k_buf + row));
                    asm volatile("cp.async.cg.shared.global [%0], [%1], 16;"
                                 :: "r"(d + 512), "l"(v_buf + row));
                }
            }
        }
        asm volatile("cp.async.commit_group;");
    };

    // Prologue: fill STAGES-1 stages.
#pragma unroll
    for (int st = 0; st < STAGES - 1; st++)
        issue_stage(st);

    // ---------------- fast path: all CHUNK tokens valid ----------------
    for (int i = 0; i < nfull; i++) {
        issue_stage(i + STAGES - 1);
        asm volatile("cp.async.wait_group %0;" :: "n"(STAGES - 1));

        const float4* kv = sbuf + (w * STAGES + (i % STAGES)) * STAGE_F4;

        const float4 kA = kv[0 * 64 + lane];
        const float4 kB = kv[1 * 64 + lane];
        const float4 kC = kv[2 * 64 + lane];
        const float4 kD = kv[3 * 64 + lane];

        float dA[GQA], dB[GQA], dC[GQA], dD[GQA];
#pragma unroll
        for (int g = 0; g < GQA; g++) {
            float a = q4[g].x * kA.x;
            a = fmaf(q4[g].y, kA.y, a); a = fmaf(q4[g].z, kA.z, a);
            a = fmaf(q4[g].w, kA.w, a); dA[g] = a;
            float c = q4[g].x * kB.x;
            c = fmaf(q4[g].y, kB.y, c); c = fmaf(q4[g].z, kB.z, c);
            c = fmaf(q4[g].w, kB.w, c); dB[g] = c;
            float e = q4[g].x * kC.x;
            e = fmaf(q4[g].y, kC.y, e); e = fmaf(q4[g].z, kC.z, e);
            e = fmaf(q4[g].w, kC.w, e); dC[g] = e;
            float f = q4[g].x * kD.x;
            f = fmaf(q4[g].y, kD.y, f); f = fmaf(q4[g].z, kD.z, f);
            f = fmaf(q4[g].w, kD.w, f); dD[g] = f;
        }
#pragma unroll
        for (int off = 16; off > 0; off >>= 1) {
#pragma unroll
            for (int g = 0; g < GQA; g++) {
                dA[g] += __shfl_xor_sync(0xFFFFFFFFu, dA[g], off);
                dB[g] += __shfl_xor_sync(0xFFFFFFFFu, dB[g], off);
                dC[g] += __shfl_xor_sync(0xFFFFFFFFu, dC[g], off);
                dD[g] += __shfl_xor_sync(0xFFFFFFFFu, dD[g], off);
            }
        }

        const float4 vA = kv[0 * 64 + 32 + lane];
        const float4 vB = kv[1 * 64 + 32 + lane];
        const float4 vC = kv[2 * 64 + 32 + lane];
        const float4 vD = kv[3 * 64 + 32 + lane];

#pragma unroll
        for (int g = 0; g < GQA; g++) {
            // all tokens valid: mn is finite, no clamp select needed
            const float mn = fmaxf(fmaxf(m[g], dA[g]),
                                   fmaxf(fmaxf(dB[g], dC[g]), dD[g]));
            const float sc = exp2f(m[g] - mn);   // exp2(-inf)=0 on first iter
            const float pA = exp2f(dA[g] - mn);
            const float pB = exp2f(dB[g] - mn);
            const float pC = exp2f(dC[g] - mn);
            const float pD = exp2f(dD[g] - mn);
            l[g] = fmaf(l[g], sc, (pA + pB) + (pC + pD));
            acc[g].x = fmaf(pD, vD.x, fmaf(pC, vC.x,
                       fmaf(pB, vB.x, fmaf(pA, vA.x, acc[g].x * sc))));
            acc[g].y = fmaf(pD, vD.y, fmaf(pC, vC.y,
                       fmaf(pB, vB.y, fmaf(pA, vA.y, acc[g].y * sc))));
            acc[g].z = fmaf(pD, vD.z, fmaf(pC, vC.z,
                       fmaf(pB, vB.z, fmaf(pA, vA.z, acc[g].z * sc))));
            acc[g].w = fmaf(pD, vD.w, fmaf(pC, vC.w,
                       fmaf(pB, vB.w, fmaf(pA, vA.w, acc[g].w * sc))));
            m[g] = mn;
        }
    }

    // ---------------- guarded tail (at most one iteration) ----------------
    for (int i = nfull; i < n_iters; i++) {
        issue_stage(i + STAGES - 1);
        asm volatile("cp.async.wait_group %0;" :: "n"(STAGES - 1));

        const float4* kv = sbuf + (w * STAGES + (i % STAGES)) * STAGE_F4;
        const int tb = t0 + i * CHUNK + w * TPI;
        const bool hA = (tb + 0) < t1;
        const bool hB = (tb + 1) < t1;
        const bool hC = (tb + 2) < t1;
        const bool hD = (tb + 3) < t1;

        const float4 kA = kv[0 * 64 + lane];
        const float4 kB = kv[1 * 64 + lane];
        const float4 kC = kv[2 * 64 + lane];
        const float4 kD = kv[3 * 64 + lane];

        float dA[GQA], dB[GQA], dC[GQA], dD[GQA];
#pragma unroll
        for (int g = 0; g < GQA; g++) {
            float a = q4[g].x * kA.x;
            a = fmaf(q4[g].y, kA.y, a); a = fmaf(q4[g].z, kA.z, a);
            a = fmaf(q4[g].w, kA.w, a); dA[g] = a;
            float c = q4[g].x * kB.x;
            c = fmaf(q4[g].y, kB.y, c); c = fmaf(q4[g].z, kB.z, c);
            c = fmaf(q4[g].w, kB.w, c); dB[g] = c;
            float e = q4[g].x * kC.x;
            e = fmaf(q4[g].y, kC.y, e); e = fmaf(q4[g].z, kC.z, e);
            e = fmaf(q4[g].w, kC.w, e); dC[g] = e;
            float f = q4[g].x * kD.x;
            f = fmaf(q4[g].y, kD.y, f); f = fmaf(q4[g].z, kD.z, f);
            f = fmaf(q4[g].w, kD.w, f); dD[g] = f;
        }
#pragma unroll
        for (int off = 16; off > 0; off >>= 1) {
#pragma unroll
            for (int g = 0; g < GQA; g++) {
                dA[g] += __shfl_xor_sync(0xFFFFFFFFu, dA[g], off);
                dB[g] += __shfl_xor_sync(0xFFFFFFFFu, dB[g], off);
                dC[g] += __shfl_xor_sync(0xFFFFFFFFu, dC[g], off);
                dD[g] += __shfl_xor_sync(0xFFFFFFFFu, dD[g], off);
            }
        }

        const float4 vA = kv[0 * 64 + 32 + lane];
        const float4 vB = kv[1 * 64 + 32 + lane];
        const float4 vC = kv[2 * 64 + 32 + lane];
        const float4 vD = kv[3 * 64 + 32 + lane];

#pragma unroll
        for (int g = 0; g < GQA; g++) {
            const float da = hA ? dA[g] : -CUDART_INF_F;
            const float db = hB ? dB[g] : -CUDART_INF_F;
            const float dc = hC ? dC[g] : -CUDART_INF_F;
            const float dd = hD ? dD[g] : -CUDART_INF_F;
            const float mn = fmaxf(fmaxf(m[g], da), fmaxf(fmaxf(db, dc), dd));
            const float mnn = (mn == -CUDART_INF_F) ? 0.0f : mn;
            const float sc = exp2f(m[g] - mnn);
            const float pA = exp2f(da - mnn);
            const float pB = exp2f(db - mnn);
            const float pC = exp2f(dc - mnn);
            const float pD = exp2f(dd - mnn);
            l[g] = fmaf(l[g], sc, (pA + pB) + (pC + pD));
            acc[g].x = fmaf(pD, vD.x, fmaf(pC, vC.x,
                       fmaf(pB, vB.x, fmaf(pA, vA.x, acc[g].x * sc))));
            acc[g].y = fmaf(pD, vD.y, fmaf(pC, vC.y,
                       fmaf(pB, vB.y, fmaf(pA, vA.y, acc[g].y * sc))));
            acc[g].z = fmaf(pD, vD.z, fmaf(pC, vC.z,
                       fmaf(pB, vB.z, fmaf(pA, vA.z, acc[g].z * sc))));
            acc[g].w = fmaf(pD, vD.w, fmaf(pC, vC.w,
                       fmaf(pB, vB.w, fmaf(pA, vA.w, acc[g].w * sc))));
            m[g] = mn;
        }
    }

    // Cross-warp combine, aliased into the staging buffer.
    __syncthreads();
    float*  sm_m   = (float*)sbuf;                       // [NWARP][GQA]
    float*  sm_l   = sm_m + NWARP * GQA;                 // [NWARP][GQA]
    float4* sm_acc = (float4*)(sm_l + NWARP * GQA);      // [NWARP][GQA][32]

    if (lane == 0) {
#pragma unroll
        for (int g = 0; g < GQA; g++) {
            sm_m[w * GQA + g] = m[g];
            sm_l[w * GQA + g] = l[g];
        }
    }
#pragma unroll
    for (int g = 0; g < GQA; g++)
        sm_acc[(w * GQA + g) * 32 + lane] = acc[g];
    __syncthreads();

    // Warp g finalizes head g
    const int g = w;
    float mf = -CUDART_INF_F;
#pragma unroll
    for (int ww = 0; ww < NWARP; ww++)
        mf = fmaxf(mf, sm_m[ww * GQA + g]);

    float  lf = 0.0f;
    float4 af = make_float4(0.f, 0.f, 0.f, 0.f);
#pragma unroll
    for (int ww = 0; ww < NWARP; ww++) {
        const float mw = sm_m[ww * GQA + g];
        const float sc = (mw == -CUDART_INF_F) ? 0.0f : exp2f(mw - mf);
        lf += sm_l[ww * GQA + g] * sc;
        const float4 a = sm_acc[(ww * GQA + g) * 32 + lane];
        af.x = fmaf(a.x, sc, af.x);
        af.y = fmaf(a.y, sc, af.y);
        af.z = fmaf(a.z, sc, af.z);
        af.w = fmaf(a.w, sc, af.w);
    }

    const float inv = (lf > 0.0f) ? (1.0f / lf) : 0.0f;
    const int   h   = hkv * GQA + g;
    const size_t ob = (((size_t)b * HEADS + h) * S_MAX + s) * DIM;
    float4 o = make_float4(af.x * inv, af.y * inv, af.z * inv, af.w * inv);
    reinterpret_cast<float4*>(att_out + ob)[lane] = o;
    if (lane == 0) {
        // m is in log2 units: lse = m*ln2 + ln(lf)
        att_lse[((size_t)b * HEADS + h) * S_MAX + s] =
            mf * 0.6931471805599453f + logf(lf);
    }
}

extern "C" void kernel_launch(void* const* d_in, const int* in_sizes, int n_in,
                              void* d_out, int out_size) {
    const float* q          = (const float*)d_in[0];
    const float* k_buffer   = (const float*)d_in[1];
    const float* v_buffer   = (const float*)d_in[2];
    const int*   kv_indptr  = (const int*)d_in[3];
    const int*   kv_indices = (const int*)d_in[4];
    const int*   nks        = (const int*)d_in[5];

    float* att_out = (float*)d_out;                                  // B*H*S*DIM
    float* att_lse = att_out + (size_t)BATCH * HEADS * S_MAX * DIM;  // B*H*S

    const int smem = NWARP * STAGES * STAGE_F4 * sizeof(float4);     // 32768
    dim3 grid(BATCH * HKV * S_MAX);
    dim3 block(NTHREAD);
    decode_attn_stage1<<<grid, block, smem>>>(q, k_buffer, v_buffer,
                                              kv_indptr, kv_indices, nks,
                                              att_out, att_lse);
}